// round 5
// baseline (speedup 1.0000x reference)
#include <cuda_runtime.h>
#include <cuda_bf16.h>
#include <mma.h>
#include <cstdint>

using namespace nvcuda;

#define NN 256
#define MATS (256LL * 256 * 256)

// scratch (static __device__ arrays: allocation-free)
__device__ __nv_bfloat16 g_Phi[MATS], g_Plo[MATS];
__device__ __nv_bfloat16 g_P2hi[MATS], g_P2lo[MATS];
__device__ float g_P2[MATS], g_P3[MATS], g_P4[MATS];

__device__ __forceinline__ uint32_t smem_u32(const void* p) {
    uint32_t a;
    asm("{ .reg .u64 t; cvta.to.shared.u64 t, %1; cvt.u32.u64 %0, t; }" : "=r"(a) : "l"(p));
    return a;
}
__device__ __forceinline__ void cpa16(uint32_t dst, const void* src) {
    asm volatile("cp.async.cg.shared.global [%0], [%1], 16;" :: "r"(dst), "l"(src));
}
__device__ __forceinline__ void cpa_commit() {
    asm volatile("cp.async.commit_group;" ::: "memory");
}
__device__ __forceinline__ void cpa_wait0() {
    asm volatile("cp.async.wait_group 0;" ::: "memory");
}

// ---------------------------------------------------------------------------
// prep: threshold + row-normalize. Warp per row, float4 loads, warp-reduce.
// Writes bf16 hi/lo of P + slots 0/1.
// ---------------------------------------------------------------------------
__global__ void __launch_bounds__(256) prep_kernel(const float* __restrict__ A,
                                                   __nv_bfloat16* __restrict__ Phi,
                                                   __nv_bfloat16* __restrict__ Plo,
                                                   float* __restrict__ out)
{
    int row = blockIdx.x * 8 + (threadIdx.x >> 5);   // global row (b*256+n)
    int lane = threadIdx.x & 31;
    int n = row & 255;

    const float* arow = A + (size_t)row * NN + lane * 8;
    float4 v0 = *(const float4*)(arow);
    float4 v1 = *(const float4*)(arow + 4);
    float f[8] = {v0.x, v0.y, v0.z, v0.w, v1.x, v1.y, v1.z, v1.w};
    float s = 0.0f;
    #pragma unroll
    for (int q = 0; q < 8; q++) {
        f[q] = (f[q] > 0.3f) ? f[q] : 0.0f;
        s += f[q];
    }
    #pragma unroll
    for (int o = 16; o; o >>= 1) s += __shfl_xor_sync(0xffffffffu, s, o);
    float dinv = (s > 0.0f) ? (1.0f / s) : 0.0f;

    uint32_t hp[4], lp[4];
    float p[8];
    #pragma unroll
    for (int q = 0; q < 4; q++) {
        p[2*q]   = f[2*q]   * dinv;
        p[2*q+1] = f[2*q+1] * dinv;
        __nv_bfloat16 h0 = __float2bfloat16_rn(p[2*q]);
        __nv_bfloat16 h1 = __float2bfloat16_rn(p[2*q+1]);
        __nv_bfloat162 hh; hh.x = h0; hh.y = h1;
        hp[q] = *(uint32_t*)&hh;
        __nv_bfloat162 ll;
        ll.x = __float2bfloat16_rn(p[2*q]   - __bfloat162float(h0));
        ll.y = __float2bfloat16_rn(p[2*q+1] - __bfloat162float(h1));
        lp[q] = *(uint32_t*)&ll;
    }
    size_t idx = (size_t)row * NN + lane * 8;
    *(uint4*)(Phi + idx) = make_uint4(hp[0], hp[1], hp[2], hp[3]);
    *(uint4*)(Plo + idx) = make_uint4(lp[0], lp[1], lp[2], lp[3]);

    if (lane == (n >> 3)) out[(size_t)row * 8 + 1] = p[n & 7];
    if (lane == 0)        out[(size_t)row * 8 + 0] = 1.0f;
}

// ---------------------------------------------------------------------------
// WMMA bf16-split GEMM: C = X * Y, row-major [M,K]x[K,N].
// CTA: 128 thr / 4 warps, tile 64x256, warp tile 64x64, K-chunk 32,
// double-buffered cp.async. Split products: XhYh + XhYl + XlYh.
// Epilogue stages C through smem (coalesced 16B stores) and writes the
// diagonal slot; if Chi != nullptr also emits bf16 hi/lo split of C.
// ---------------------------------------------------------------------------
#define XLD 40                                // 32 + 8 pad
#define YLD 264                               // 256 + 8 pad
#define XARR_B (64 * XLD * 2)                 // 5120
#define YARR_B (32 * YLD * 2)                 // 16896
#define OFF_XL XARR_B                         // 5120
#define OFF_YH (2 * XARR_B)                   // 10240
#define OFF_YL (2 * XARR_B + YARR_B)          // 27136
#define STAGE_B (2 * XARR_B + 2 * YARR_B)     // 44032
#define GEMM_SMEM (2 * STAGE_B)               // 88064  (epilogue: 64*260*4=66560 fits)
#define CLD 260

__global__ void __launch_bounds__(128, 2)
gemm_wmma(const __nv_bfloat16* __restrict__ Xh0, const __nv_bfloat16* __restrict__ Xl0,
          const __nv_bfloat16* __restrict__ Yh0, const __nv_bfloat16* __restrict__ Yl0,
          float* __restrict__ C0, __nv_bfloat16* Chi0, __nv_bfloat16* Clo0, int slot0,
          const __nv_bfloat16* __restrict__ Xh1, const __nv_bfloat16* __restrict__ Xl1,
          const __nv_bfloat16* __restrict__ Yh1, const __nv_bfloat16* __restrict__ Yl1,
          float* __restrict__ C1, __nv_bfloat16* Chi1, __nv_bfloat16* Clo1, int slot1,
          float* __restrict__ out)
{
    const __nv_bfloat16* Xh = blockIdx.z ? Xh1 : Xh0;
    const __nv_bfloat16* Xl = blockIdx.z ? Xl1 : Xl0;
    const __nv_bfloat16* Yh = blockIdx.z ? Yh1 : Yh0;
    const __nv_bfloat16* Yl = blockIdx.z ? Yl1 : Yl0;
    float* C = blockIdx.z ? C1 : C0;
    __nv_bfloat16* Chi = blockIdx.z ? Chi1 : Chi0;
    __nv_bfloat16* Clo = blockIdx.z ? Clo1 : Clo0;
    int slot = blockIdx.z ? slot1 : slot0;

    int b = blockIdx.y;
    size_t base = (size_t)b << 16;
    Xh += base; Xl += base; Yh += base; Yl += base; C += base;
    if (Chi) { Chi += base; Clo += base; }
    int tileM = blockIdx.x << 6;                 // 0,64,128,192

    extern __shared__ __align__(128) char sm[];
    uint32_t smb = smem_u32(sm);

    int t = threadIdx.x;
    int w = t >> 5;                              // warp 0..3 -> cols w*64
    int wcol = w << 6;

    // loader splits
    int xr = t >> 1, xq = t & 1;                 // X: 64 rows x 2x32B
    int yr = t >> 2, yq = t & 3;                 // Y: 32 rows x 4x128B

    wmma::fragment<wmma::accumulator, 16, 16, 16, float> acc[4][4];
    #pragma unroll
    for (int i = 0; i < 4; i++)
        #pragma unroll
        for (int j = 0; j < 4; j++) wmma::fill_fragment(acc[i][j], 0.0f);

    auto issue = [&](int kc, int s) {
        int k0 = kc << 5;
        uint32_t sb = smb + s * STAGE_B;
        {   // X: 64 rows x 64B per array
            const __nv_bfloat16* gh = Xh + (size_t)(tileM + xr) * NN + k0 + xq * 16;
            const __nv_bfloat16* gl = Xl + (size_t)(tileM + xr) * NN + k0 + xq * 16;
            uint32_t d = sb + xr * (XLD * 2) + xq * 32;
            cpa16(d, gh);           cpa16(d + 16, gh + 8);
            cpa16(d + OFF_XL, gl);  cpa16(d + OFF_XL + 16, gl + 8);
        }
        {   // Y: 32 rows x 512B per array; thread covers 128B (8x16B)
            const __nv_bfloat16* gh = Yh + (size_t)(k0 + yr) * NN + yq * 64;
            const __nv_bfloat16* gl = Yl + (size_t)(k0 + yr) * NN + yq * 64;
            uint32_t d = sb + OFF_YH + yr * (YLD * 2) + yq * 128;
            #pragma unroll
            for (int k = 0; k < 8; k++) {
                cpa16(d + k * 16, gh + k * 8);
                cpa16(d + (OFF_YL - OFF_YH) + k * 16, gl + k * 8);
            }
        }
        cpa_commit();
    };

    issue(0, 0);

    #pragma unroll 1
    for (int kc = 0; kc < 8; kc++) {
        int s = kc & 1;
        cpa_wait0();
        __syncthreads();
        if (kc < 7) issue(kc + 1, s ^ 1);

        const __nv_bfloat16* bXh = (const __nv_bfloat16*)(sm + s * STAGE_B);
        const __nv_bfloat16* bXl = (const __nv_bfloat16*)(sm + s * STAGE_B + OFF_XL);
        const __nv_bfloat16* bYh = (const __nv_bfloat16*)(sm + s * STAGE_B + OFF_YH);
        const __nv_bfloat16* bYl = (const __nv_bfloat16*)(sm + s * STAGE_B + OFF_YL);

        #pragma unroll
        for (int kk = 0; kk < 2; kk++) {
            int ks = kk * 16;
            wmma::fragment<wmma::matrix_a, 16, 16, 16, __nv_bfloat16, wmma::row_major> ah[4], al[4];
            #pragma unroll
            for (int i = 0; i < 4; i++) {
                wmma::load_matrix_sync(ah[i], bXh + (i * 16) * XLD + ks, XLD);
                wmma::load_matrix_sync(al[i], bXl + (i * 16) * XLD + ks, XLD);
            }
            #pragma unroll
            for (int j = 0; j < 4; j++) {
                wmma::fragment<wmma::matrix_b, 16, 16, 16, __nv_bfloat16, wmma::row_major> bh, bl;
                wmma::load_matrix_sync(bh, bYh + ks * YLD + wcol + j * 16, YLD);
                wmma::load_matrix_sync(bl, bYl + ks * YLD + wcol + j * 16, YLD);
                #pragma unroll
                for (int i = 0; i < 4; i++) {
                    wmma::mma_sync(acc[i][j], ah[i], bh, acc[i][j]);
                    wmma::mma_sync(acc[i][j], ah[i], bl, acc[i][j]);
                    wmma::mma_sync(acc[i][j], al[i], bh, acc[i][j]);
                }
            }
        }
        __syncthreads();
    }

    // epilogue: stage 64x256 fp32 in smem (ld=CLD), then coalesced writes
    float* cs = (float*)sm;
    #pragma unroll
    for (int i = 0; i < 4; i++)
        #pragma unroll
        for (int j = 0; j < 4; j++)
            wmma::store_matrix_sync(cs + (i * 16) * CLD + wcol + j * 16,
                                    acc[i][j], CLD, wmma::mem_row_major);
    __syncthreads();

    #pragma unroll
    for (int it = 0; it < 16; it++) {
        int idx = t + it * 128;            // 2048 chunks of 8 floats
        int r = idx >> 5;                  // 64 rows
        int c = (idx & 31) << 3;           // 32 chunks x 8
        const float* sp = cs + r * CLD + c;
        float4 v0 = *(const float4*)(sp);
        float4 v1 = *(const float4*)(sp + 4);
        int gr = tileM + r;
        float* cp = C + (size_t)gr * NN + c;
        *(float4*)cp = v0;
        *(float4*)(cp + 4) = v1;

        if (((gr >> 3) << 3) == c) {       // diagonal element lives in this chunk
            float f8[8] = {v0.x, v0.y, v0.z, v0.w, v1.x, v1.y, v1.z, v1.w};
            out[((size_t)b * NN + gr) * 8 + slot] = f8[gr & 7];
        }

        if (Chi) {
            float f[8] = {v0.x, v0.y, v0.z, v0.w, v1.x, v1.y, v1.z, v1.w};
            uint32_t hp[4], lp[4];
            #pragma unroll
            for (int q = 0; q < 4; q++) {
                __nv_bfloat16 h0 = __float2bfloat16_rn(f[2*q]);
                __nv_bfloat16 h1 = __float2bfloat16_rn(f[2*q+1]);
                __nv_bfloat162 hh; hh.x = h0; hh.y = h1;
                hp[q] = *(uint32_t*)&hh;
                __nv_bfloat162 ll;
                ll.x = __float2bfloat16_rn(f[2*q]   - __bfloat162float(h0));
                ll.y = __float2bfloat16_rn(f[2*q+1] - __bfloat162float(h1));
                lp[q] = *(uint32_t*)&ll;
            }
            *(uint4*)(Chi + (size_t)gr * NN + c) = make_uint4(hp[0], hp[1], hp[2], hp[3]);
            *(uint4*)(Clo + (size_t)gr * NN + c) = make_uint4(lp[0], lp[1], lp[2], lp[3]);
        }
    }
}

// ---------------------------------------------------------------------------
// diag3: slots 5,6,7 with smem-transposed (coalesced) column reads.
// d5 = <P2[i,:], P3[:,i]>, d6 = <P3[i,:], P3[:,i]>, d7 = <P3[i,:], P4[:,i]>
// ---------------------------------------------------------------------------
__global__ void __launch_bounds__(256) diag3_kernel(const float* __restrict__ P2,
                                                    const float* __restrict__ P3,
                                                    const float* __restrict__ P4,
                                                    float* __restrict__ out)
{
    __shared__ float c3[32][33], c4[32][33];
    int b = blockIdx.x >> 3;
    int i0 = (blockIdx.x & 7) << 5;
    size_t base = (size_t)b << 16;
    int t = threadIdx.x;
    int il = t >> 3, jq = t & 7;
    int lc = t & 31, lr = t >> 5;

    const float* r2 = P2 + base + (size_t)(i0 + il) * NN;
    const float* r3 = P3 + base + (size_t)(i0 + il) * NN;

    float a5 = 0.f, a6 = 0.f, a7 = 0.f;
    #pragma unroll 1
    for (int jt = 0; jt < 8; jt++) {
        int j0 = jt << 5;
        #pragma unroll
        for (int qq = 0; qq < 4; qq++) {
            int jl = lr + qq * 8;
            size_t src = base + (size_t)(j0 + jl) * NN + i0 + lc;
            c3[jl][lc] = P3[src];
            c4[jl][lc] = P4[src];
        }
        __syncthreads();
        float4 x2 = *(const float4*)(r2 + j0 + jq * 4);
        float4 x3 = *(const float4*)(r3 + j0 + jq * 4);
        int jb = jq * 4;
        a5 = fmaf(x2.x, c3[jb+0][il], a5); a5 = fmaf(x2.y, c3[jb+1][il], a5);
        a5 = fmaf(x2.z, c3[jb+2][il], a5); a5 = fmaf(x2.w, c3[jb+3][il], a5);
        a6 = fmaf(x3.x, c3[jb+0][il], a6); a6 = fmaf(x3.y, c3[jb+1][il], a6);
        a6 = fmaf(x3.z, c3[jb+2][il], a6); a6 = fmaf(x3.w, c3[jb+3][il], a6);
        a7 = fmaf(x3.x, c4[jb+0][il], a7); a7 = fmaf(x3.y, c4[jb+1][il], a7);
        a7 = fmaf(x3.z, c4[jb+2][il], a7); a7 = fmaf(x3.w, c4[jb+3][il], a7);
        __syncthreads();
    }
    #pragma unroll
    for (int o = 4; o; o >>= 1) {
        a5 += __shfl_down_sync(0xffffffffu, a5, o);
        a6 += __shfl_down_sync(0xffffffffu, a6, o);
        a7 += __shfl_down_sync(0xffffffffu, a7, o);
    }
    if (jq == 0) {
        size_t o = ((size_t)b * NN + i0 + il) * 8;
        out[o + 5] = a5;
        out[o + 6] = a6;
        out[o + 7] = a7;
    }
}

// ---------------------------------------------------------------------------
extern "C" void kernel_launch(void* const* d_in, const int* in_sizes, int n_in,
                              void* d_out, int out_size)
{
    const float* A = (const float*)d_in[0];
    float* out = (float*)d_out;

    __nv_bfloat16 *Phi, *Plo, *P2hi, *P2lo;
    float *P2, *P3, *P4;
    cudaGetSymbolAddress((void**)&Phi,  g_Phi);
    cudaGetSymbolAddress((void**)&Plo,  g_Plo);
    cudaGetSymbolAddress((void**)&P2hi, g_P2hi);
    cudaGetSymbolAddress((void**)&P2lo, g_P2lo);
    cudaGetSymbolAddress((void**)&P2, g_P2);
    cudaGetSymbolAddress((void**)&P3, g_P3);
    cudaGetSymbolAddress((void**)&P4, g_P4);

    cudaFuncSetAttribute(gemm_wmma, cudaFuncAttributeMaxDynamicSharedMemorySize, GEMM_SMEM);

    // 1) P (bf16 hi/lo) + slots 0,1
    prep_kernel<<<8192, 256>>>(A, Phi, Plo, out);
    // 2) P2 = P * P  (fp32 + fused bf16 hi/lo split) + slot 2
    gemm_wmma<<<dim3(4, 256, 1), 128, GEMM_SMEM>>>(
        Phi, Plo, Phi, Plo, P2, P2hi, P2lo, 2,
        Phi, Plo, Phi, Plo, P2, P2hi, P2lo, 2, out);
    // 3) P3 = P*P2 (slot 3), P4 = P2*P2 (slot 4), dual launch
    gemm_wmma<<<dim3(4, 256, 2), 128, GEMM_SMEM>>>(
        Phi,  Plo,  P2hi, P2lo, P3, nullptr, nullptr, 3,
        P2hi, P2lo, P2hi, P2lo, P4, nullptr, nullptr, 4, out);
    // 4) slots 5,6,7
    diag3_kernel<<<256 * 8, 256>>>(P2, P3, P4, out);
}

// round 6
// speedup vs baseline: 1.2762x; 1.2762x over previous
#include <cuda_runtime.h>
#include <cuda_bf16.h>
#include <mma.h>
#include <cstdint>

using namespace nvcuda;

#define NN 256
#define MATS (256LL * 256 * 256)

// scratch (static __device__ arrays: allocation-free)
__device__ __nv_bfloat16 g_Phi[MATS], g_Plo[MATS];
__device__ __nv_bfloat16 g_P2hi[MATS], g_P2lo[MATS];
__device__ float g_P2[MATS], g_P3[MATS], g_P4[MATS];

__device__ __forceinline__ uint32_t smem_u32(const void* p) {
    uint32_t a;
    asm("{ .reg .u64 t; cvta.to.shared.u64 t, %1; cvt.u32.u64 %0, t; }" : "=r"(a) : "l"(p));
    return a;
}
__device__ __forceinline__ void cpa16(uint32_t dst, const void* src) {
    asm volatile("cp.async.cg.shared.global [%0], [%1], 16;" :: "r"(dst), "l"(src));
}
__device__ __forceinline__ void cpa_commit() {
    asm volatile("cp.async.commit_group;" ::: "memory");
}
__device__ __forceinline__ void cpa_wait0() {
    asm volatile("cp.async.wait_group 0;" ::: "memory");
}

// ---------------------------------------------------------------------------
// prep: threshold + row-normalize. Warp per row, float4 loads, warp-reduce.
// Writes bf16 hi/lo of P + slots 0/1.
// ---------------------------------------------------------------------------
__global__ void __launch_bounds__(256) prep_kernel(const float* __restrict__ A,
                                                   __nv_bfloat16* __restrict__ Phi,
                                                   __nv_bfloat16* __restrict__ Plo,
                                                   float* __restrict__ out)
{
    int row = blockIdx.x * 8 + (threadIdx.x >> 5);   // global row (b*256+n)
    int lane = threadIdx.x & 31;
    int n = row & 255;

    const float* arow = A + (size_t)row * NN + lane * 8;
    float4 v0 = *(const float4*)(arow);
    float4 v1 = *(const float4*)(arow + 4);
    float f[8] = {v0.x, v0.y, v0.z, v0.w, v1.x, v1.y, v1.z, v1.w};
    float s = 0.0f;
    #pragma unroll
    for (int q = 0; q < 8; q++) {
        f[q] = (f[q] > 0.3f) ? f[q] : 0.0f;
        s += f[q];
    }
    #pragma unroll
    for (int o = 16; o; o >>= 1) s += __shfl_xor_sync(0xffffffffu, s, o);
    float dinv = (s > 0.0f) ? (1.0f / s) : 0.0f;

    uint32_t hp[4], lp[4];
    float p[8];
    #pragma unroll
    for (int q = 0; q < 4; q++) {
        p[2*q]   = f[2*q]   * dinv;
        p[2*q+1] = f[2*q+1] * dinv;
        __nv_bfloat16 h0 = __float2bfloat16_rn(p[2*q]);
        __nv_bfloat16 h1 = __float2bfloat16_rn(p[2*q+1]);
        __nv_bfloat162 hh; hh.x = h0; hh.y = h1;
        hp[q] = *(uint32_t*)&hh;
        __nv_bfloat162 ll;
        ll.x = __float2bfloat16_rn(p[2*q]   - __bfloat162float(h0));
        ll.y = __float2bfloat16_rn(p[2*q+1] - __bfloat162float(h1));
        lp[q] = *(uint32_t*)&ll;
    }
    size_t idx = (size_t)row * NN + lane * 8;
    *(uint4*)(Phi + idx) = make_uint4(hp[0], hp[1], hp[2], hp[3]);
    *(uint4*)(Plo + idx) = make_uint4(lp[0], lp[1], lp[2], lp[3]);

    if (lane == (n >> 3)) out[(size_t)row * 8 + 1] = p[n & 7];
    if (lane == 0)        out[(size_t)row * 8 + 0] = 1.0f;
}

// ---------------------------------------------------------------------------
// WMMA bf16-split GEMM (R4-proven config): C = X * Y, row-major [M,K]x[K,N].
// CTA: 256 thr / 8 warps, tile 128x128, warp tile 64x32, K-chunk 32,
// double-buffered smem via cp.async. 3 split products: XhYh + XhYl + XlYh.
// If Chi != nullptr: epilogue also emits bf16 hi/lo split of C (fused, via
// smem staging).
// ---------------------------------------------------------------------------
#define XLD 40                               // X smem ld (elems): 32 + 8 pad
#define YLD 136                              // Y smem ld (elems): 128 + 8 pad
#define XARR_B (128 * XLD * 2)               // 10240
#define YARR_B (32 * YLD * 2)                // 8704
#define OFF_XL XARR_B                        // 10240
#define OFF_YH (2 * XARR_B)                  // 20480
#define OFF_YL (2 * XARR_B + YARR_B)         // 29184
#define STAGE_B (2 * XARR_B + 2 * YARR_B)    // 37888
#define GEMM_SMEM (2 * STAGE_B)              // 75776  (epilogue staging 128*132*4=67584 fits)

__global__ void __launch_bounds__(256, 2)
gemm_wmma(const __nv_bfloat16* __restrict__ Xh0, const __nv_bfloat16* __restrict__ Xl0,
          const __nv_bfloat16* __restrict__ Yh0, const __nv_bfloat16* __restrict__ Yl0,
          float* __restrict__ C0, __nv_bfloat16* Chi0, __nv_bfloat16* Clo0,
          const __nv_bfloat16* __restrict__ Xh1, const __nv_bfloat16* __restrict__ Xl1,
          const __nv_bfloat16* __restrict__ Yh1, const __nv_bfloat16* __restrict__ Yl1,
          float* __restrict__ C1, __nv_bfloat16* Chi1, __nv_bfloat16* Clo1)
{
    const __nv_bfloat16* Xh = blockIdx.z ? Xh1 : Xh0;
    const __nv_bfloat16* Xl = blockIdx.z ? Xl1 : Xl0;
    const __nv_bfloat16* Yh = blockIdx.z ? Yh1 : Yh0;
    const __nv_bfloat16* Yl = blockIdx.z ? Yl1 : Yl0;
    float* C = blockIdx.z ? C1 : C0;
    __nv_bfloat16* Chi = blockIdx.z ? Chi1 : Chi0;
    __nv_bfloat16* Clo = blockIdx.z ? Clo1 : Clo0;

    size_t base = (size_t)blockIdx.y << 16;
    Xh += base; Xl += base; Yh += base; Yl += base; C += base;
    if (Chi) { Chi += base; Clo += base; }
    int tileM = (blockIdx.x >> 1) << 7;
    int tileN = (blockIdx.x & 1) << 7;

    extern __shared__ __align__(128) char sm[];
    uint32_t smb = smem_u32(sm);

    int t = threadIdx.x;
    int w = t >> 5, wm = w & 1, wn = w >> 1;   // warp tile: rows wm*64, cols wn*32

    // loader index splits
    int xr = t >> 1, xq = t & 1;   // X: 128 rows x 2x32B
    int yr = t >> 4, yq = t & 15;  // Y: 32 rows x 16x16B

    wmma::fragment<wmma::accumulator, 16, 16, 16, float> acc[4][2];
    #pragma unroll
    for (int i = 0; i < 4; i++)
        #pragma unroll
        for (int j = 0; j < 2; j++) wmma::fill_fragment(acc[i][j], 0.0f);

    // issue one K-chunk (32 cols of X / 32 rows of Y) into stage s
    auto issue = [&](int kc, int s) {
        int k0 = kc << 5;
        uint32_t sb = smb + s * STAGE_B;
        {
            const __nv_bfloat16* gh = Xh + (size_t)(tileM + xr) * NN + k0 + xq * 16;
            const __nv_bfloat16* gl = Xl + (size_t)(tileM + xr) * NN + k0 + xq * 16;
            uint32_t d = sb + xr * (XLD * 2) + xq * 32;
            cpa16(d, gh);               cpa16(d + 16, gh + 8);
            cpa16(d + OFF_XL, gl);      cpa16(d + OFF_XL + 16, gl + 8);
        }
        {
            const __nv_bfloat16* gh = Yh + (size_t)(k0 + yr) * NN + tileN + yq * 8;
            const __nv_bfloat16* gl = Yl + (size_t)(k0 + yr) * NN + tileN + yq * 8;
            uint32_t d = sb + OFF_YH + yr * (YLD * 2) + yq * 16;
            cpa16(d, gh);               cpa16(d + 16 * (YLD * 2), gh + 16 * NN);
            cpa16(d + YARR_B, gl);      cpa16(d + YARR_B + 16 * (YLD * 2), gl + 16 * NN);
        }
        cpa_commit();
    };

    issue(0, 0);

    #pragma unroll 1
    for (int kc = 0; kc < 8; kc++) {
        int s = kc & 1;
        cpa_wait0();
        __syncthreads();
        if (kc < 7) issue(kc + 1, s ^ 1);

        const __nv_bfloat16* bXh = (const __nv_bfloat16*)(sm + s * STAGE_B);
        const __nv_bfloat16* bXl = (const __nv_bfloat16*)(sm + s * STAGE_B + OFF_XL);
        const __nv_bfloat16* bYh = (const __nv_bfloat16*)(sm + s * STAGE_B + OFF_YH);
        const __nv_bfloat16* bYl = (const __nv_bfloat16*)(sm + s * STAGE_B + OFF_YL);

        #pragma unroll
        for (int kk = 0; kk < 2; kk++) {
            int ks = kk * 16;
            wmma::fragment<wmma::matrix_a, 16, 16, 16, __nv_bfloat16, wmma::row_major> ah[4], al[4];
            wmma::fragment<wmma::matrix_b, 16, 16, 16, __nv_bfloat16, wmma::row_major> bh[2], bl[2];
            #pragma unroll
            for (int i = 0; i < 4; i++) {
                wmma::load_matrix_sync(ah[i], bXh + (wm * 64 + i * 16) * XLD + ks, XLD);
                wmma::load_matrix_sync(al[i], bXl + (wm * 64 + i * 16) * XLD + ks, XLD);
            }
            #pragma unroll
            for (int j = 0; j < 2; j++) {
                wmma::load_matrix_sync(bh[j], bYh + ks * YLD + wn * 32 + j * 16, YLD);
                wmma::load_matrix_sync(bl[j], bYl + ks * YLD + wn * 32 + j * 16, YLD);
            }
            #pragma unroll
            for (int i = 0; i < 4; i++)
                #pragma unroll
                for (int j = 0; j < 2; j++) {
                    wmma::mma_sync(acc[i][j], ah[i], bh[j], acc[i][j]);
                    wmma::mma_sync(acc[i][j], ah[i], bl[j], acc[i][j]);
                    wmma::mma_sync(acc[i][j], al[i], bh[j], acc[i][j]);
                }
        }
        __syncthreads();
    }

    if (!Chi) {
        // plain fp32 epilogue
        #pragma unroll
        for (int i = 0; i < 4; i++)
            #pragma unroll
            for (int j = 0; j < 2; j++) {
                float* cp = C + (size_t)(tileM + wm * 64 + i * 16) * NN + tileN + wn * 32 + j * 16;
                wmma::store_matrix_sync(cp, acc[i][j], NN, wmma::mem_row_major);
            }
    } else {
        // fused split epilogue via smem staging (128x132 fp32)
        float* cs = (float*)sm;
        #pragma unroll
        for (int i = 0; i < 4; i++)
            #pragma unroll
            for (int j = 0; j < 2; j++)
                wmma::store_matrix_sync(cs + (wm * 64 + i * 16) * 132 + wn * 32 + j * 16,
                                        acc[i][j], 132, wmma::mem_row_major);
        __syncthreads();
        #pragma unroll
        for (int it = 0; it < 8; it++) {
            int idx = t + it * 256;          // 2048 chunks of 8 floats
            int r = idx >> 4;                // 128 rows
            int c = (idx & 15) << 3;         // 16 chunks x 8 floats
            const float* sp = cs + r * 132 + c;
            float4 v0 = *(const float4*)(sp);
            float4 v1 = *(const float4*)(sp + 4);
            float* cp = C + (size_t)(tileM + r) * NN + tileN + c;
            *(float4*)cp = v0;
            *(float4*)(cp + 4) = v1;

            float f[8] = {v0.x, v0.y, v0.z, v0.w, v1.x, v1.y, v1.z, v1.w};
            uint32_t hp[4], lp[4];
            #pragma unroll
            for (int q = 0; q < 4; q++) {
                __nv_bfloat16 h0 = __float2bfloat16_rn(f[2*q]);
                __nv_bfloat16 h1 = __float2bfloat16_rn(f[2*q+1]);
                __nv_bfloat162 hh; hh.x = h0; hh.y = h1;
                hp[q] = *(uint32_t*)&hh;
                __nv_bfloat162 ll;
                ll.x = __float2bfloat16_rn(f[2*q]   - __bfloat162float(h0));
                ll.y = __float2bfloat16_rn(f[2*q+1] - __bfloat162float(h1));
                lp[q] = *(uint32_t*)&ll;
            }
            *(uint4*)(Chi + (size_t)(tileM + r) * NN + tileN + c) = make_uint4(hp[0], hp[1], hp[2], hp[3]);
            *(uint4*)(Clo + (size_t)(tileM + r) * NN + tileN + c) = make_uint4(lp[0], lp[1], lp[2], lp[3]);
        }
    }
}

// ---------------------------------------------------------------------------
// diag3: slots 5,6,7 via smem-transposed (coalesced) column reads; slots
// 2,3,4 folded in (diag elements come out of the staged c3/c4 tiles + one
// strided P2 read) — no separate diag_extract launch.
// d5 = <P2[i,:], P3[:,i]>, d6 = <P3[i,:], P3[:,i]>, d7 = <P3[i,:], P4[:,i]>
// ---------------------------------------------------------------------------
__global__ void __launch_bounds__(256) diag3_kernel(const float* __restrict__ P2,
                                                    const float* __restrict__ P3,
                                                    const float* __restrict__ P4,
                                                    float* __restrict__ out)
{
    __shared__ float c3[32][33], c4[32][33];
    int b = blockIdx.x >> 3;
    int i0 = (blockIdx.x & 7) << 5;
    size_t base = (size_t)b << 16;
    int t = threadIdx.x;
    int il = t >> 3, jq = t & 7;
    int lc = t & 31, lr = t >> 5;

    const float* r2 = P2 + base + (size_t)(i0 + il) * NN;
    const float* r3 = P3 + base + (size_t)(i0 + il) * NN;

    float a5 = 0.f, a6 = 0.f, a7 = 0.f;
    #pragma unroll 1
    for (int jt = 0; jt < 8; jt++) {
        int j0 = jt << 5;
        #pragma unroll
        for (int qq = 0; qq < 4; qq++) {
            int jl = lr + qq * 8;
            size_t src = base + (size_t)(j0 + jl) * NN + i0 + lc;
            c3[jl][lc] = P3[src];
            c4[jl][lc] = P4[src];
        }
        __syncthreads();

        if (jt == (i0 >> 5) && t < 32) {
            // diagonal elements of P3,P4 live in this tile; P2 diag direct
            size_t o = ((size_t)b * NN + i0 + t) * 8;
            out[o + 2] = P2[base + (size_t)(i0 + t) * (NN + 1)];
            out[o + 3] = c3[t][t];
            out[o + 4] = c4[t][t];
        }

        float4 x2 = *(const float4*)(r2 + j0 + jq * 4);
        float4 x3 = *(const float4*)(r3 + j0 + jq * 4);
        int jb = jq * 4;
        a5 = fmaf(x2.x, c3[jb+0][il], a5); a5 = fmaf(x2.y, c3[jb+1][il], a5);
        a5 = fmaf(x2.z, c3[jb+2][il], a5); a5 = fmaf(x2.w, c3[jb+3][il], a5);
        a6 = fmaf(x3.x, c3[jb+0][il], a6); a6 = fmaf(x3.y, c3[jb+1][il], a6);
        a6 = fmaf(x3.z, c3[jb+2][il], a6); a6 = fmaf(x3.w, c3[jb+3][il], a6);
        a7 = fmaf(x3.x, c4[jb+0][il], a7); a7 = fmaf(x3.y, c4[jb+1][il], a7);
        a7 = fmaf(x3.z, c4[jb+2][il], a7); a7 = fmaf(x3.w, c4[jb+3][il], a7);
        __syncthreads();
    }
    #pragma unroll
    for (int o = 4; o; o >>= 1) {
        a5 += __shfl_down_sync(0xffffffffu, a5, o);
        a6 += __shfl_down_sync(0xffffffffu, a6, o);
        a7 += __shfl_down_sync(0xffffffffu, a7, o);
    }
    if (jq == 0) {
        size_t o = ((size_t)b * NN + i0 + il) * 8;
        out[o + 5] = a5;
        out[o + 6] = a6;
        out[o + 7] = a7;
    }
}

// ---------------------------------------------------------------------------
extern "C" void kernel_launch(void* const* d_in, const int* in_sizes, int n_in,
                              void* d_out, int out_size)
{
    const float* A = (const float*)d_in[0];
    float* out = (float*)d_out;

    __nv_bfloat16 *Phi, *Plo, *P2hi, *P2lo;
    float *P2, *P3, *P4;
    cudaGetSymbolAddress((void**)&Phi,  g_Phi);
    cudaGetSymbolAddress((void**)&Plo,  g_Plo);
    cudaGetSymbolAddress((void**)&P2hi, g_P2hi);
    cudaGetSymbolAddress((void**)&P2lo, g_P2lo);
    cudaGetSymbolAddress((void**)&P2, g_P2);
    cudaGetSymbolAddress((void**)&P3, g_P3);
    cudaGetSymbolAddress((void**)&P4, g_P4);

    cudaFuncSetAttribute(gemm_wmma, cudaFuncAttributeMaxDynamicSharedMemorySize, GEMM_SMEM);

    // 1) P (bf16 hi/lo) + slots 0,1
    prep_kernel<<<8192, 256>>>(A, Phi, Plo, out);
    // 2) P2 = P * P  (fp32 + fused bf16 hi/lo split)
    gemm_wmma<<<dim3(4, 256, 1), 256, GEMM_SMEM>>>(
        Phi, Plo, Phi, Plo, P2, P2hi, P2lo,
        Phi, Plo, Phi, Plo, P2, P2hi, P2lo);
    // 3) P3 = P*P2, P4 = P2*P2 (dual launch, fp32 only)
    gemm_wmma<<<dim3(4, 256, 2), 256, GEMM_SMEM>>>(
        Phi,  Plo,  P2hi, P2lo, P3, nullptr, nullptr,
        P2hi, P2lo, P2hi, P2lo, P4, nullptr, nullptr);
    // 4) slots 2..7
    diag3_kernel<<<256 * 8, 256>>>(P2, P3, P4, out);
}

// round 7
// speedup vs baseline: 1.2871x; 1.0086x over previous
#include <cuda_runtime.h>
#include <cuda_bf16.h>
#include <mma.h>
#include <cstdint>

using namespace nvcuda;

#define NN 256
#define MATS (256LL * 256 * 256)

// scratch (static __device__ arrays: allocation-free)
__device__ __nv_bfloat16 g_Phi[MATS], g_Plo[MATS];
__device__ __nv_bfloat16 g_P2hi[MATS], g_P2lo[MATS];
__device__ __nv_bfloat16 g_P3hi[MATS], g_P3lo[MATS];
__device__ float g_d7p[2 * 65536];          // d7 partials [tileM/128][b*256+i]

__device__ __forceinline__ uint32_t smem_u32(const void* p) {
    uint32_t a;
    asm("{ .reg .u64 t; cvta.to.shared.u64 t, %1; cvt.u32.u64 %0, t; }" : "=r"(a) : "l"(p));
    return a;
}
__device__ __forceinline__ void cpa16(uint32_t dst, const void* src) {
    asm volatile("cp.async.cg.shared.global [%0], [%1], 16;" :: "r"(dst), "l"(src));
}
__device__ __forceinline__ void cpa_commit() {
    asm volatile("cp.async.commit_group;" ::: "memory");
}
__device__ __forceinline__ void cpa_wait0() {
    asm volatile("cp.async.wait_group 0;" ::: "memory");
}
__device__ __forceinline__ float bf2f(__nv_bfloat16 v) { return __bfloat162float(v); }

// ---------------------------------------------------------------------------
// prep: threshold + row-normalize. Warp per row, float4 loads, warp-reduce.
// Writes bf16 hi/lo of P + slots 0/1.
// ---------------------------------------------------------------------------
__global__ void __launch_bounds__(256) prep_kernel(const float* __restrict__ A,
                                                   __nv_bfloat16* __restrict__ Phi,
                                                   __nv_bfloat16* __restrict__ Plo,
                                                   float* __restrict__ out)
{
    int row = blockIdx.x * 8 + (threadIdx.x >> 5);   // global row (b*256+n)
    int lane = threadIdx.x & 31;
    int n = row & 255;

    const float* arow = A + (size_t)row * NN + lane * 8;
    float4 v0 = *(const float4*)(arow);
    float4 v1 = *(const float4*)(arow + 4);
    float f[8] = {v0.x, v0.y, v0.z, v0.w, v1.x, v1.y, v1.z, v1.w};
    float s = 0.0f;
    #pragma unroll
    for (int q = 0; q < 8; q++) {
        f[q] = (f[q] > 0.3f) ? f[q] : 0.0f;
        s += f[q];
    }
    #pragma unroll
    for (int o = 16; o; o >>= 1) s += __shfl_xor_sync(0xffffffffu, s, o);
    float dinv = (s > 0.0f) ? (1.0f / s) : 0.0f;

    uint32_t hp[4], lp[4];
    float p[8];
    #pragma unroll
    for (int q = 0; q < 4; q++) {
        p[2*q]   = f[2*q]   * dinv;
        p[2*q+1] = f[2*q+1] * dinv;
        __nv_bfloat16 h0 = __float2bfloat16_rn(p[2*q]);
        __nv_bfloat16 h1 = __float2bfloat16_rn(p[2*q+1]);
        __nv_bfloat162 hh; hh.x = h0; hh.y = h1;
        hp[q] = *(uint32_t*)&hh;
        __nv_bfloat162 ll;
        ll.x = __float2bfloat16_rn(p[2*q]   - bf2f(h0));
        ll.y = __float2bfloat16_rn(p[2*q+1] - bf2f(h1));
        lp[q] = *(uint32_t*)&ll;
    }
    size_t idx = (size_t)row * NN + lane * 8;
    *(uint4*)(Phi + idx) = make_uint4(hp[0], hp[1], hp[2], hp[3]);
    *(uint4*)(Plo + idx) = make_uint4(lp[0], lp[1], lp[2], lp[3]);

    if (lane == (n >> 3)) out[(size_t)row * 8 + 1] = p[n & 7];
    if (lane == 0)        out[(size_t)row * 8 + 0] = 1.0f;
}

// ---------------------------------------------------------------------------
// WMMA bf16-split GEMM: C = X * Y, row-major [M,K]x[K,N].
// CTA: 256 thr / 8 warps, tile 128x128, warp tile 64x32, K-chunk 32,
// double-buffered cp.async. 3 split products: XhYh + XhYl + XlYh.
// Epilogue mode A (Chi != null): write bf16 hi/lo of C + diag slot.
// Epilogue mode B (Chi == null): C NOT stored; diag slot + d7 partials
//   d7p[tileM/128][b*256+i] = sum_{j in tileM-tile} P3[i,j] * C[j,i]
// ---------------------------------------------------------------------------
#define XLD 40
#define YLD 136
#define XARR_B (128 * XLD * 2)               // 10240
#define YARR_B (32 * YLD * 2)                // 8704
#define OFF_XL XARR_B
#define OFF_YH (2 * XARR_B)
#define OFF_YL (2 * XARR_B + YARR_B)
#define STAGE_B (2 * XARR_B + 2 * YARR_B)    // 37888  -> mainloop 75776
#define CLD 132                              // C stage ld (mult of 4; conflict-free cols)
#define SLD 132                              // P3 slab ld
#define CS_B (128 * CLD * 4)                 // 67584
#define SP3_OFF CS_B                         // P3 slab after cs
#define GEMM_SMEM (CS_B + 32 * SLD * 4)      // 84480 (>= 75776 mainloop)

__global__ void __launch_bounds__(256, 2)
gemm_wmma(const __nv_bfloat16* __restrict__ Xh, const __nv_bfloat16* __restrict__ Xl,
          const __nv_bfloat16* __restrict__ Yh, const __nv_bfloat16* __restrict__ Yl,
          __nv_bfloat16* __restrict__ Chi, __nv_bfloat16* __restrict__ Clo, int slot,
          const __nv_bfloat16* __restrict__ P3h, const __nv_bfloat16* __restrict__ P3l,
          float* __restrict__ d7p, float* __restrict__ out)
{
    int b = blockIdx.y;
    size_t base = (size_t)b << 16;
    Xh += base; Xl += base; Yh += base; Yl += base;
    if (Chi) { Chi += base; Clo += base; }
    int tileM = (blockIdx.x >> 1) << 7;
    int tileN = (blockIdx.x & 1) << 7;

    extern __shared__ __align__(128) char sm[];
    uint32_t smb = smem_u32(sm);

    int t = threadIdx.x;
    int w = t >> 5, wm = w & 1, wn = w >> 1;

    int xr = t >> 1, xq = t & 1;   // X: 128 rows x 2x32B
    int yr = t >> 4, yq = t & 15;  // Y: 32 rows x 16x16B

    wmma::fragment<wmma::accumulator, 16, 16, 16, float> acc[4][2];
    #pragma unroll
    for (int i = 0; i < 4; i++)
        #pragma unroll
        for (int j = 0; j < 2; j++) wmma::fill_fragment(acc[i][j], 0.0f);

    auto issue = [&](int kc, int s) {
        int k0 = kc << 5;
        uint32_t sb = smb + s * STAGE_B;
        {
            const __nv_bfloat16* gh = Xh + (size_t)(tileM + xr) * NN + k0 + xq * 16;
            const __nv_bfloat16* gl = Xl + (size_t)(tileM + xr) * NN + k0 + xq * 16;
            uint32_t d = sb + xr * (XLD * 2) + xq * 32;
            cpa16(d, gh);               cpa16(d + 16, gh + 8);
            cpa16(d + OFF_XL, gl);      cpa16(d + OFF_XL + 16, gl + 8);
        }
        {
            const __nv_bfloat16* gh = Yh + (size_t)(k0 + yr) * NN + tileN + yq * 8;
            const __nv_bfloat16* gl = Yl + (size_t)(k0 + yr) * NN + tileN + yq * 8;
            uint32_t d = sb + OFF_YH + yr * (YLD * 2) + yq * 16;
            cpa16(d, gh);               cpa16(d + 16 * (YLD * 2), gh + 16 * NN);
            cpa16(d + YARR_B, gl);      cpa16(d + YARR_B + 16 * (YLD * 2), gl + 16 * NN);
        }
        cpa_commit();
    };

    issue(0, 0);

    #pragma unroll 1
    for (int kc = 0; kc < 8; kc++) {
        int s = kc & 1;
        cpa_wait0();
        __syncthreads();
        if (kc < 7) issue(kc + 1, s ^ 1);

        const __nv_bfloat16* bXh = (const __nv_bfloat16*)(sm + s * STAGE_B);
        const __nv_bfloat16* bXl = (const __nv_bfloat16*)(sm + s * STAGE_B + OFF_XL);
        const __nv_bfloat16* bYh = (const __nv_bfloat16*)(sm + s * STAGE_B + OFF_YH);
        const __nv_bfloat16* bYl = (const __nv_bfloat16*)(sm + s * STAGE_B + OFF_YL);

        #pragma unroll
        for (int kk = 0; kk < 2; kk++) {
            int ks = kk * 16;
            wmma::fragment<wmma::matrix_a, 16, 16, 16, __nv_bfloat16, wmma::row_major> ah[4], al[4];
            wmma::fragment<wmma::matrix_b, 16, 16, 16, __nv_bfloat16, wmma::row_major> bh[2], bl[2];
            #pragma unroll
            for (int i = 0; i < 4; i++) {
                wmma::load_matrix_sync(ah[i], bXh + (wm * 64 + i * 16) * XLD + ks, XLD);
                wmma::load_matrix_sync(al[i], bXl + (wm * 64 + i * 16) * XLD + ks, XLD);
            }
            #pragma unroll
            for (int j = 0; j < 2; j++) {
                wmma::load_matrix_sync(bh[j], bYh + ks * YLD + wn * 32 + j * 16, YLD);
                wmma::load_matrix_sync(bl[j], bYl + ks * YLD + wn * 32 + j * 16, YLD);
            }
            #pragma unroll
            for (int i = 0; i < 4; i++)
                #pragma unroll
                for (int j = 0; j < 2; j++) {
                    wmma::mma_sync(acc[i][j], ah[i], bh[j], acc[i][j]);
                    wmma::mma_sync(acc[i][j], ah[i], bl[j], acc[i][j]);
                    wmma::mma_sync(acc[i][j], al[i], bh[j], acc[i][j]);
                }
        }
        __syncthreads();
    }

    // stage full 128x128 fp32 tile in smem
    float* cs = (float*)sm;
    #pragma unroll
    for (int i = 0; i < 4; i++)
        #pragma unroll
        for (int j = 0; j < 2; j++)
            wmma::store_matrix_sync(cs + (wm * 64 + i * 16) * CLD + wn * 32 + j * 16,
                                    acc[i][j], CLD, wmma::mem_row_major);
    __syncthreads();

    // diag slot (diagonal blocks only)
    if (tileM == tileN && t < 128)
        out[((size_t)(b << 8) + tileM + t) * 8 + slot] = cs[t * CLD + t];

    if (Chi) {
        // mode A: bf16 hi/lo split of C
        #pragma unroll
        for (int it = 0; it < 8; it++) {
            int idx = t + it * 256;          // 2048 chunks of 8 floats
            int r = idx >> 4;
            int c = (idx & 15) << 3;
            const float* sp = cs + r * CLD + c;
            float f[8];
            #pragma unroll
            for (int q = 0; q < 8; q++) f[q] = sp[q];
            uint32_t hp[4], lp[4];
            #pragma unroll
            for (int q = 0; q < 4; q++) {
                __nv_bfloat16 h0 = __float2bfloat16_rn(f[2*q]);
                __nv_bfloat16 h1 = __float2bfloat16_rn(f[2*q+1]);
                __nv_bfloat162 hh; hh.x = h0; hh.y = h1;
                hp[q] = *(uint32_t*)&hh;
                __nv_bfloat162 ll;
                ll.x = __float2bfloat16_rn(f[2*q]   - bf2f(h0));
                ll.y = __float2bfloat16_rn(f[2*q+1] - bf2f(h1));
                lp[q] = *(uint32_t*)&ll;
            }
            *(uint4*)(Chi + (size_t)(tileM + r) * NN + tileN + c) = make_uint4(hp[0], hp[1], hp[2], hp[3]);
            *(uint4*)(Clo + (size_t)(tileM + r) * NN + tileN + c) = make_uint4(lp[0], lp[1], lp[2], lp[3]);
        }
    } else {
        // mode B: d7 partials. C tile = P4[j in tileM.., i in tileN..].
        // partial_i = sum_j P3[i, tileM+j] * cs[j][i_loc]
        float* sp3 = (float*)(sm + SP3_OFF);           // [32][SLD]
        const __nv_bfloat16* p3h = P3h + base;
        const __nv_bfloat16* p3l = P3l + base;
        int il = t >> 3, jq = t & 7;
        #pragma unroll 1
        for (int s4 = 0; s4 < 4; s4++) {
            // load slab: P3 rows (tileN + s4*32 + row), cols tileM..+128, coalesced
            {
                int rrow = t >> 3;             // 0..31
                int sc = (t & 7) * 16;         // 16 bf16 per thread
                size_t gidx = (size_t)(tileN + s4 * 32 + rrow) * NN + tileM + sc;
                uint4 uh0 = *(const uint4*)(p3h + gidx);
                uint4 uh1 = *(const uint4*)(p3h + gidx + 8);
                uint4 ul0 = *(const uint4*)(p3l + gidx);
                uint4 ul1 = *(const uint4*)(p3l + gidx + 8);
                const uint32_t uh[8] = {uh0.x,uh0.y,uh0.z,uh0.w,uh1.x,uh1.y,uh1.z,uh1.w};
                const uint32_t ul[8] = {ul0.x,ul0.y,ul0.z,ul0.w,ul1.x,ul1.y,ul1.z,ul1.w};
                float* dst = sp3 + rrow * SLD + sc;
                #pragma unroll
                for (int q = 0; q < 8; q++) {
                    __nv_bfloat162 h = *(__nv_bfloat162*)&uh[q];
                    __nv_bfloat162 l = *(__nv_bfloat162*)&ul[q];
                    dst[2*q]   = bf2f(h.x) + bf2f(l.x);
                    dst[2*q+1] = bf2f(h.y) + bf2f(l.y);
                }
            }
            __syncthreads();
            int i_loc = s4 * 32 + il;
            float a = 0.0f;
            #pragma unroll
            for (int k = 0; k < 16; k++) {
                int j = jq + k * 8;
                a = fmaf(sp3[il * SLD + j], cs[j * CLD + i_loc], a);
            }
            a += __shfl_down_sync(0xffffffffu, a, 4);
            a += __shfl_down_sync(0xffffffffu, a, 2);
            a += __shfl_down_sync(0xffffffffu, a, 1);
            if (jq == 0)
                d7p[(tileM >> 7) * 65536 + (b << 8) + tileN + i_loc] = a;
            __syncthreads();
        }
    }
}

// ---------------------------------------------------------------------------
// diag3: d5 = <P2[i,:], P3[:,i]>, d6 = <P3[i,:], P3[:,i]> via smem-transposed
// coalesced column reads; d7 = sum of precomputed partials.
// Inputs are bf16 hi/lo pairs, reconstructed on the fly.
// ---------------------------------------------------------------------------
__global__ void __launch_bounds__(256) diag3_kernel(const __nv_bfloat16* __restrict__ P2h,
                                                    const __nv_bfloat16* __restrict__ P2l,
                                                    const __nv_bfloat16* __restrict__ P3h,
                                                    const __nv_bfloat16* __restrict__ P3l,
                                                    const float* __restrict__ d7p,
                                                    float* __restrict__ out)
{
    __shared__ float c3[32][33];
    int b = blockIdx.x >> 3;
    int i0 = (blockIdx.x & 7) << 5;
    size_t base = (size_t)b << 16;
    int t = threadIdx.x;
    int il = t >> 3, jq = t & 7;
    int lc = t & 31, lr = t >> 5;

    const __nv_bfloat16* r2h = P2h + base + (size_t)(i0 + il) * NN;
    const __nv_bfloat16* r2l = P2l + base + (size_t)(i0 + il) * NN;
    const __nv_bfloat16* r3h = P3h + base + (size_t)(i0 + il) * NN;
    const __nv_bfloat16* r3l = P3l + base + (size_t)(i0 + il) * NN;

    float a5 = 0.f, a6 = 0.f;
    #pragma unroll 1
    for (int jt = 0; jt < 8; jt++) {
        int j0 = jt << 5;
        #pragma unroll
        for (int qq = 0; qq < 4; qq++) {
            int jl = lr + qq * 8;
            size_t src = base + (size_t)(j0 + jl) * NN + i0 + lc;
            c3[jl][lc] = bf2f(P3h[src]) + bf2f(P3l[src]);
        }
        __syncthreads();

        // row segments: 4 elems at j0 + jq*4 (8B-aligned)
        uint2 u2h = *(const uint2*)(r2h + j0 + jq * 4);
        uint2 u2l = *(const uint2*)(r2l + j0 + jq * 4);
        uint2 u3h = *(const uint2*)(r3h + j0 + jq * 4);
        uint2 u3l = *(const uint2*)(r3l + j0 + jq * 4);
        float x2[4], x3[4];
        {
            __nv_bfloat162 h0 = *(__nv_bfloat162*)&u2h.x, h1 = *(__nv_bfloat162*)&u2h.y;
            __nv_bfloat162 l0 = *(__nv_bfloat162*)&u2l.x, l1 = *(__nv_bfloat162*)&u2l.y;
            x2[0] = bf2f(h0.x) + bf2f(l0.x); x2[1] = bf2f(h0.y) + bf2f(l0.y);
            x2[2] = bf2f(h1.x) + bf2f(l1.x); x2[3] = bf2f(h1.y) + bf2f(l1.y);
        }
        {
            __nv_bfloat162 h0 = *(__nv_bfloat162*)&u3h.x, h1 = *(__nv_bfloat162*)&u3h.y;
            __nv_bfloat162 l0 = *(__nv_bfloat162*)&u3l.x, l1 = *(__nv_bfloat162*)&u3l.y;
            x3[0] = bf2f(h0.x) + bf2f(l0.x); x3[1] = bf2f(h0.y) + bf2f(l0.y);
            x3[2] = bf2f(h1.x) + bf2f(l1.x); x3[3] = bf2f(h1.y) + bf2f(l1.y);
        }
        int jb = jq * 4;
        #pragma unroll
        for (int k = 0; k < 4; k++) {
            float cc = c3[jb + k][il];
            a5 = fmaf(x2[k], cc, a5);
            a6 = fmaf(x3[k], cc, a6);
        }
        __syncthreads();
    }
    #pragma unroll
    for (int o = 4; o; o >>= 1) {
        a5 += __shfl_down_sync(0xffffffffu, a5, o);
        a6 += __shfl_down_sync(0xffffffffu, a6, o);
    }
    if (jq == 0) {
        int gi = (b << 8) + i0 + il;
        size_t o = (size_t)gi * 8;
        out[o + 5] = a5;
        out[o + 6] = a6;
        out[o + 7] = d7p[gi] + d7p[65536 + gi];
    }
}

// ---------------------------------------------------------------------------
extern "C" void kernel_launch(void* const* d_in, const int* in_sizes, int n_in,
                              void* d_out, int out_size)
{
    const float* A = (const float*)d_in[0];
    float* out = (float*)d_out;

    __nv_bfloat16 *Phi, *Plo, *P2hi, *P2lo, *P3hi, *P3lo;
    float* d7p;
    cudaGetSymbolAddress((void**)&Phi,  g_Phi);
    cudaGetSymbolAddress((void**)&Plo,  g_Plo);
    cudaGetSymbolAddress((void**)&P2hi, g_P2hi);
    cudaGetSymbolAddress((void**)&P2lo, g_P2lo);
    cudaGetSymbolAddress((void**)&P3hi, g_P3hi);
    cudaGetSymbolAddress((void**)&P3lo, g_P3lo);
    cudaGetSymbolAddress((void**)&d7p,  g_d7p);

    cudaFuncSetAttribute(gemm_wmma, cudaFuncAttributeMaxDynamicSharedMemorySize, GEMM_SMEM);

    // 1) P (bf16 hi/lo) + slots 0,1
    prep_kernel<<<8192, 256>>>(A, Phi, Plo, out);
    // 2) P2 = P * P (bf16 hi/lo only) + slot 2
    gemm_wmma<<<dim3(4, 256), 256, GEMM_SMEM>>>(
        Phi, Plo, Phi, Plo, P2hi, P2lo, 2, nullptr, nullptr, nullptr, out);
    // 3) P3 = P * P2 (bf16 hi/lo only) + slot 3
    gemm_wmma<<<dim3(4, 256), 256, GEMM_SMEM>>>(
        Phi, Plo, P2hi, P2lo, P3hi, P3lo, 3, nullptr, nullptr, nullptr, out);
    // 4) P4 = P2 * P2 — never stored; slot 4 + d7 partials
    gemm_wmma<<<dim3(4, 256), 256, GEMM_SMEM>>>(
        P2hi, P2lo, P2hi, P2lo, nullptr, nullptr, 4, P3hi, P3lo, d7p, out);
    // 5) slots 5,6,7
    diag3_kernel<<<2048, 256>>>(P2hi, P2lo, P3hi, P3lo, d7p, out);
}

// round 8
// speedup vs baseline: 1.3114x; 1.0189x over previous
#include <cuda_runtime.h>
#include <cuda_bf16.h>
#include <mma.h>
#include <cstdint>

using namespace nvcuda;

#define NN 256
#define MATS (256LL * 256 * 256)

// scratch (static __device__ arrays: allocation-free)
__device__ __nv_bfloat16 g_Phi[MATS], g_Plo[MATS];
__device__ __nv_bfloat16 g_P2hi[MATS], g_P2lo[MATS];
__device__ __nv_bfloat16 g_P3hi[MATS], g_P3lo[MATS];
__device__ __nv_bfloat16 g_P4hi[MATS], g_P4lo[MATS];

__device__ __forceinline__ uint32_t smem_u32(const void* p) {
    uint32_t a;
    asm("{ .reg .u64 t; cvta.to.shared.u64 t, %1; cvt.u32.u64 %0, t; }" : "=r"(a) : "l"(p));
    return a;
}
__device__ __forceinline__ void cpa16(uint32_t dst, const void* src) {
    asm volatile("cp.async.cg.shared.global [%0], [%1], 16;" :: "r"(dst), "l"(src));
}
__device__ __forceinline__ void cpa_commit() {
    asm volatile("cp.async.commit_group;" ::: "memory");
}
__device__ __forceinline__ float bf2f(__nv_bfloat16 v) { return __bfloat162float(v); }

// ---------------------------------------------------------------------------
// prep: threshold + row-normalize. Warp per row, float4 loads, warp-reduce.
// Writes bf16 hi/lo of P + slots 0/1.
// ---------------------------------------------------------------------------
__global__ void __launch_bounds__(256) prep_kernel(const float* __restrict__ A,
                                                   __nv_bfloat16* __restrict__ Phi,
                                                   __nv_bfloat16* __restrict__ Plo,
                                                   float* __restrict__ out)
{
    int row = blockIdx.x * 8 + (threadIdx.x >> 5);   // global row (b*256+n)
    int lane = threadIdx.x & 31;
    int n = row & 255;

    const float* arow = A + (size_t)row * NN + lane * 8;
    float4 v0 = *(const float4*)(arow);
    float4 v1 = *(const float4*)(arow + 4);
    float f[8] = {v0.x, v0.y, v0.z, v0.w, v1.x, v1.y, v1.z, v1.w};
    float s = 0.0f;
    #pragma unroll
    for (int q = 0; q < 8; q++) {
        f[q] = (f[q] > 0.3f) ? f[q] : 0.0f;
        s += f[q];
    }
    #pragma unroll
    for (int o = 16; o; o >>= 1) s += __shfl_xor_sync(0xffffffffu, s, o);
    float dinv = (s > 0.0f) ? (1.0f / s) : 0.0f;

    uint32_t hp[4], lp[4];
    float p[8];
    #pragma unroll
    for (int q = 0; q < 4; q++) {
        p[2*q]   = f[2*q]   * dinv;
        p[2*q+1] = f[2*q+1] * dinv;
        __nv_bfloat16 h0 = __float2bfloat16_rn(p[2*q]);
        __nv_bfloat16 h1 = __float2bfloat16_rn(p[2*q+1]);
        __nv_bfloat162 hh; hh.x = h0; hh.y = h1;
        hp[q] = *(uint32_t*)&hh;
        __nv_bfloat162 ll;
        ll.x = __float2bfloat16_rn(p[2*q]   - bf2f(h0));
        ll.y = __float2bfloat16_rn(p[2*q+1] - bf2f(h1));
        lp[q] = *(uint32_t*)&ll;
    }
    size_t idx = (size_t)row * NN + lane * 8;
    *(uint4*)(Phi + idx) = make_uint4(hp[0], hp[1], hp[2], hp[3]);
    *(uint4*)(Plo + idx) = make_uint4(lp[0], lp[1], lp[2], lp[3]);

    if (lane == (n >> 3)) out[(size_t)row * 8 + 1] = p[n & 7];
    if (lane == 0)        out[(size_t)row * 8 + 0] = 1.0f;
}

// ---------------------------------------------------------------------------
// WMMA bf16-split GEMM: C = X * Y, row-major [M,K]x[K,N].
// CTA: 256 thr / 8 warps, tile 128x128, warp tile 64x32, K-chunk 32,
// THREE-stage cp.async pipeline (depth 2), single sync per chunk.
// 3 split products: XhYh + XhYl + XlYh.
// Epilogue: smem-staged C -> bf16 hi/lo + diag slot.
// blockIdx.z selects one of two problem descriptors (dual launch).
// ---------------------------------------------------------------------------
#define XLD 40
#define YLD 136
#define XARR_B (128 * XLD * 2)               // 10240
#define YARR_B (32 * YLD * 2)                // 8704
#define OFF_XL XARR_B
#define OFF_YH (2 * XARR_B)
#define OFF_YL (2 * XARR_B + YARR_B)
#define STAGE_B (2 * XARR_B + 2 * YARR_B)    // 37888
#define GEMM_SMEM (3 * STAGE_B)              // 113664 (2 CTA/SM: 227328 <= 228KB)
#define CLD 132                              // epilogue stage ld; 128*132*4=67584 fits

__global__ void __launch_bounds__(256, 2)
gemm_wmma(const __nv_bfloat16* __restrict__ Xh0, const __nv_bfloat16* __restrict__ Xl0,
          const __nv_bfloat16* __restrict__ Yh0, const __nv_bfloat16* __restrict__ Yl0,
          __nv_bfloat16* __restrict__ Chi0, __nv_bfloat16* __restrict__ Clo0, int slot0,
          const __nv_bfloat16* __restrict__ Xh1, const __nv_bfloat16* __restrict__ Xl1,
          const __nv_bfloat16* __restrict__ Yh1, const __nv_bfloat16* __restrict__ Yl1,
          __nv_bfloat16* __restrict__ Chi1, __nv_bfloat16* __restrict__ Clo1, int slot1,
          float* __restrict__ out)
{
    const __nv_bfloat16* Xh = blockIdx.z ? Xh1 : Xh0;
    const __nv_bfloat16* Xl = blockIdx.z ? Xl1 : Xl0;
    const __nv_bfloat16* Yh = blockIdx.z ? Yh1 : Yh0;
    const __nv_bfloat16* Yl = blockIdx.z ? Yl1 : Yl0;
    __nv_bfloat16* Chi = blockIdx.z ? Chi1 : Chi0;
    __nv_bfloat16* Clo = blockIdx.z ? Clo1 : Clo0;
    int slot = blockIdx.z ? slot1 : slot0;

    int b = blockIdx.y;
    size_t base = (size_t)b << 16;
    Xh += base; Xl += base; Yh += base; Yl += base;
    Chi += base; Clo += base;
    int tileM = (blockIdx.x >> 1) << 7;
    int tileN = (blockIdx.x & 1) << 7;

    extern __shared__ __align__(128) char sm[];
    uint32_t smb = smem_u32(sm);

    int t = threadIdx.x;
    int w = t >> 5, wm = w & 1, wn = w >> 1;

    int xr = t >> 1, xq = t & 1;   // X: 128 rows x 2x32B
    int yr = t >> 4, yq = t & 15;  // Y: 32 rows x 16x16B

    wmma::fragment<wmma::accumulator, 16, 16, 16, float> acc[4][2];
    #pragma unroll
    for (int i = 0; i < 4; i++)
        #pragma unroll
        for (int j = 0; j < 2; j++) wmma::fill_fragment(acc[i][j], 0.0f);

    auto issue = [&](int kc, int s) {
        int k0 = kc << 5;
        uint32_t sb = smb + s * STAGE_B;
        {
            const __nv_bfloat16* gh = Xh + (size_t)(tileM + xr) * NN + k0 + xq * 16;
            const __nv_bfloat16* gl = Xl + (size_t)(tileM + xr) * NN + k0 + xq * 16;
            uint32_t d = sb + xr * (XLD * 2) + xq * 32;
            cpa16(d, gh);               cpa16(d + 16, gh + 8);
            cpa16(d + OFF_XL, gl);      cpa16(d + OFF_XL + 16, gl + 8);
        }
        {
            const __nv_bfloat16* gh = Yh + (size_t)(k0 + yr) * NN + tileN + yq * 8;
            const __nv_bfloat16* gl = Yl + (size_t)(k0 + yr) * NN + tileN + yq * 8;
            uint32_t d = sb + OFF_YH + yr * (YLD * 2) + yq * 16;
            cpa16(d, gh);               cpa16(d + 16 * (YLD * 2), gh + 16 * NN);
            cpa16(d + YARR_B, gl);      cpa16(d + YARR_B + 16 * (YLD * 2), gl + 16 * NN);
        }
        cpa_commit();
    };

    issue(0, 0);
    issue(1, 1);

    int scur = 0, sis = 2;
    #pragma unroll 1
    for (int kc = 0; kc < 8; kc++) {
        if (kc < 6) asm volatile("cp.async.wait_group 1;" ::: "memory");
        else        asm volatile("cp.async.wait_group 0;" ::: "memory");
        __syncthreads();
        if (kc < 6) issue(kc + 2, sis);

        const char* sb = sm + scur * STAGE_B;
        const __nv_bfloat16* bXh = (const __nv_bfloat16*)(sb);
        const __nv_bfloat16* bXl = (const __nv_bfloat16*)(sb + OFF_XL);
        const __nv_bfloat16* bYh = (const __nv_bfloat16*)(sb + OFF_YH);
        const __nv_bfloat16* bYl = (const __nv_bfloat16*)(sb + OFF_YL);

        #pragma unroll
        for (int kk = 0; kk < 2; kk++) {
            int ks = kk * 16;
            wmma::fragment<wmma::matrix_a, 16, 16, 16, __nv_bfloat16, wmma::row_major> ah[4], al[4];
            wmma::fragment<wmma::matrix_b, 16, 16, 16, __nv_bfloat16, wmma::row_major> bh[2], bl[2];
            #pragma unroll
            for (int i = 0; i < 4; i++) {
                wmma::load_matrix_sync(ah[i], bXh + (wm * 64 + i * 16) * XLD + ks, XLD);
                wmma::load_matrix_sync(al[i], bXl + (wm * 64 + i * 16) * XLD + ks, XLD);
            }
            #pragma unroll
            for (int j = 0; j < 2; j++) {
                wmma::load_matrix_sync(bh[j], bYh + ks * YLD + wn * 32 + j * 16, YLD);
                wmma::load_matrix_sync(bl[j], bYl + ks * YLD + wn * 32 + j * 16, YLD);
            }
            #pragma unroll
            for (int i = 0; i < 4; i++)
                #pragma unroll
                for (int j = 0; j < 2; j++) {
                    wmma::mma_sync(acc[i][j], ah[i], bh[j], acc[i][j]);
                    wmma::mma_sync(acc[i][j], ah[i], bl[j], acc[i][j]);
                    wmma::mma_sync(acc[i][j], al[i], bh[j], acc[i][j]);
                }
        }
        scur = (scur == 2) ? 0 : scur + 1;
        sis  = (sis  == 2) ? 0 : sis + 1;
        __syncthreads();
    }

    // epilogue: stage 128x128 fp32 tile in smem, emit bf16 hi/lo + diag slot
    float* cs = (float*)sm;
    #pragma unroll
    for (int i = 0; i < 4; i++)
        #pragma unroll
        for (int j = 0; j < 2; j++)
            wmma::store_matrix_sync(cs + (wm * 64 + i * 16) * CLD + wn * 32 + j * 16,
                                    acc[i][j], CLD, wmma::mem_row_major);
    __syncthreads();

    if (tileM == tileN && t < 128)
        out[((size_t)(b << 8) + tileM + t) * 8 + slot] = cs[t * CLD + t];

    #pragma unroll
    for (int it = 0; it < 8; it++) {
        int idx = t + it * 256;          // 2048 chunks of 8 floats
        int r = idx >> 4;
        int c = (idx & 15) << 3;
        const float* sp = cs + r * CLD + c;
        float f[8];
        #pragma unroll
        for (int q = 0; q < 8; q++) f[q] = sp[q];
        uint32_t hp[4], lp[4];
        #pragma unroll
        for (int q = 0; q < 4; q++) {
            __nv_bfloat16 h0 = __float2bfloat16_rn(f[2*q]);
            __nv_bfloat16 h1 = __float2bfloat16_rn(f[2*q+1]);
            __nv_bfloat162 hh; hh.x = h0; hh.y = h1;
            hp[q] = *(uint32_t*)&hh;
            __nv_bfloat162 ll;
            ll.x = __float2bfloat16_rn(f[2*q]   - bf2f(h0));
            ll.y = __float2bfloat16_rn(f[2*q+1] - bf2f(h1));
            lp[q] = *(uint32_t*)&ll;
        }
        *(uint4*)(Chi + (size_t)(tileM + r) * NN + tileN + c) = make_uint4(hp[0], hp[1], hp[2], hp[3]);
        *(uint4*)(Clo + (size_t)(tileM + r) * NN + tileN + c) = make_uint4(lp[0], lp[1], lp[2], lp[3]);
    }
}

// ---------------------------------------------------------------------------
// diag3: d5 = <P2[i,:], P3[:,i]>, d6 = <P3[i,:], P3[:,i]>,
//        d7 = <P3[i,:], P4[:,i]>. Columns staged through smem (coalesced),
//        all inputs bf16 hi/lo reconstructed.
// ---------------------------------------------------------------------------
__global__ void __launch_bounds__(256) diag3_kernel(const __nv_bfloat16* __restrict__ P2h,
                                                    const __nv_bfloat16* __restrict__ P2l,
                                                    const __nv_bfloat16* __restrict__ P3h,
                                                    const __nv_bfloat16* __restrict__ P3l,
                                                    const __nv_bfloat16* __restrict__ P4h,
                                                    const __nv_bfloat16* __restrict__ P4l,
                                                    float* __restrict__ out)
{
    __shared__ float c3[32][33], c4[32][33];
    int b = blockIdx.x >> 3;
    int i0 = (blockIdx.x & 7) << 5;
    size_t base = (size_t)b << 16;
    int t = threadIdx.x;
    int il = t >> 3, jq = t & 7;
    int lc = t & 31, lr = t >> 5;

    const __nv_bfloat16* r2h = P2h + base + (size_t)(i0 + il) * NN;
    const __nv_bfloat16* r2l = P2l + base + (size_t)(i0 + il) * NN;
    const __nv_bfloat16* r3h = P3h + base + (size_t)(i0 + il) * NN;
    const __nv_bfloat16* r3l = P3l + base + (size_t)(i0 + il) * NN;

    float a5 = 0.f, a6 = 0.f, a7 = 0.f;
    #pragma unroll 1
    for (int jt = 0; jt < 8; jt++) {
        int j0 = jt << 5;
        #pragma unroll
        for (int qq = 0; qq < 4; qq++) {
            int jl = lr + qq * 8;
            size_t src = base + (size_t)(j0 + jl) * NN + i0 + lc;
            c3[jl][lc] = bf2f(P3h[src]) + bf2f(P3l[src]);
            c4[jl][lc] = bf2f(P4h[src]) + bf2f(P4l[src]);
        }
        __syncthreads();

        uint2 u2h = *(const uint2*)(r2h + j0 + jq * 4);
        uint2 u2l = *(const uint2*)(r2l + j0 + jq * 4);
        uint2 u3h = *(const uint2*)(r3h + j0 + jq * 4);
        uint2 u3l = *(const uint2*)(r3l + j0 + jq * 4);
        float x2[4], x3[4];
        {
            __nv_bfloat162 h0 = *(__nv_bfloat162*)&u2h.x, h1 = *(__nv_bfloat162*)&u2h.y;
            __nv_bfloat162 l0 = *(__nv_bfloat162*)&u2l.x, l1 = *(__nv_bfloat162*)&u2l.y;
            x2[0] = bf2f(h0.x) + bf2f(l0.x); x2[1] = bf2f(h0.y) + bf2f(l0.y);
            x2[2] = bf2f(h1.x) + bf2f(l1.x); x2[3] = bf2f(h1.y) + bf2f(l1.y);
        }
        {
            __nv_bfloat162 h0 = *(__nv_bfloat162*)&u3h.x, h1 = *(__nv_bfloat162*)&u3h.y;
            __nv_bfloat162 l0 = *(__nv_bfloat162*)&u3l.x, l1 = *(__nv_bfloat162*)&u3l.y;
            x3[0] = bf2f(h0.x) + bf2f(l0.x); x3[1] = bf2f(h0.y) + bf2f(l0.y);
            x3[2] = bf2f(h1.x) + bf2f(l1.x); x3[3] = bf2f(h1.y) + bf2f(l1.y);
        }
        int jb = jq * 4;
        #pragma unroll
        for (int k = 0; k < 4; k++) {
            float cc3 = c3[jb + k][il];
            float cc4 = c4[jb + k][il];
            a5 = fmaf(x2[k], cc3, a5);
            a6 = fmaf(x3[k], cc3, a6);
            a7 = fmaf(x3[k], cc4, a7);
        }
        __syncthreads();
    }
    #pragma unroll
    for (int o = 4; o; o >>= 1) {
        a5 += __shfl_down_sync(0xffffffffu, a5, o);
        a6 += __shfl_down_sync(0xffffffffu, a6, o);
        a7 += __shfl_down_sync(0xffffffffu, a7, o);
    }
    if (jq == 0) {
        size_t o = ((size_t)(b << 8) + i0 + il) * 8;
        out[o + 5] = a5;
        out[o + 6] = a6;
        out[o + 7] = a7;
    }
}

// ---------------------------------------------------------------------------
extern "C" void kernel_launch(void* const* d_in, const int* in_sizes, int n_in,
                              void* d_out, int out_size)
{
    const float* A = (const float*)d_in[0];
    float* out = (float*)d_out;

    __nv_bfloat16 *Phi, *Plo, *P2hi, *P2lo, *P3hi, *P3lo, *P4hi, *P4lo;
    cudaGetSymbolAddress((void**)&Phi,  g_Phi);
    cudaGetSymbolAddress((void**)&Plo,  g_Plo);
    cudaGetSymbolAddress((void**)&P2hi, g_P2hi);
    cudaGetSymbolAddress((void**)&P2lo, g_P2lo);
    cudaGetSymbolAddress((void**)&P3hi, g_P3hi);
    cudaGetSymbolAddress((void**)&P3lo, g_P3lo);
    cudaGetSymbolAddress((void**)&P4hi, g_P4hi);
    cudaGetSymbolAddress((void**)&P4lo, g_P4lo);

    cudaFuncSetAttribute(gemm_wmma, cudaFuncAttributeMaxDynamicSharedMemorySize, GEMM_SMEM);

    // 1) P (bf16 hi/lo) + slots 0,1
    prep_kernel<<<8192, 256>>>(A, Phi, Plo, out);
    // 2) P2 = P * P (bf16 hi/lo) + slot 2
    gemm_wmma<<<dim3(4, 256, 1), 256, GEMM_SMEM>>>(
        Phi, Plo, Phi, Plo, P2hi, P2lo, 2,
        Phi, Plo, Phi, Plo, P2hi, P2lo, 2, out);
    // 3) dual launch: P3 = P*P2 (slot 3) and P4 = P2*P2 (slot 4)
    gemm_wmma<<<dim3(4, 256, 2), 256, GEMM_SMEM>>>(
        Phi,  Plo,  P2hi, P2lo, P3hi, P3lo, 3,
        P2hi, P2lo, P2hi, P2lo, P4hi, P4lo, 4, out);
    // 4) slots 5,6,7
    diag3_kernel<<<2048, 256>>>(P2hi, P2lo, P3hi, P3lo, P4hi, P4lo, out);
}